// round 11
// baseline (speedup 1.0000x reference)
#include <cuda_runtime.h>

typedef unsigned long long u64;

#define NTHREADS 256
#define GRID_BLOCKS 2048   // 1048576 elems / (2 per thread * 256)

// ---------- weights in constant memory (uniform-port loads) ----------
__constant__ __align__(16) float c_wih[96];    // [48][2] row-major
__constant__ __align__(16) float c_whh[768];   // [48][16] row-major
__constant__ __align__(16) float c_bih[48];
__constant__ __align__(16) float c_bhh[48];
__constant__ __align__(16) float c_wsum[16];
__constant__ __align__(16) float c_wcar[16];
__constant__ float c_bsum[1];
__constant__ float c_bcar[1];

// ---------- packed f32x2 + approx-math helpers ----------
__device__ __forceinline__ u64 f2fma(u64 a, u64 b, u64 c) {
    u64 d; asm("fma.rn.f32x2 %0, %1, %2, %3;" : "=l"(d) : "l"(a), "l"(b), "l"(c)); return d;
}
__device__ __forceinline__ u64 pk2(float lo, float hi) {
    u64 d; asm("mov.b64 %0, {%1,%2};" : "=l"(d) : "f"(lo), "f"(hi)); return d;
}
__device__ __forceinline__ void up2(u64 a, float& lo, float& hi) {
    asm("mov.b64 {%0,%1}, %2;" : "=f"(lo), "=f"(hi) : "l"(a));
}
__device__ __forceinline__ float hsum(u64 a) {   // lo + hi
    float lo, hi; up2(a, lo, hi); return lo + hi;
}
__device__ __forceinline__ float ex2f(float x) {
    float y; asm("ex2.approx.f32 %0, %1;" : "=f"(y) : "f"(x)); return y;
}
__device__ __forceinline__ float rcpf(float x) {
    float y; asm("rcp.approx.f32 %0, %1;" : "=f"(y) : "f"(x)); return y;
}
__device__ __forceinline__ float sigmoidf_(float a) {
    return rcpf(1.0f + ex2f(-1.4426950408889634f * a));
}
__device__ __forceinline__ float tanhf_(float a) {
    return fmaf(2.0f, rcpf(1.0f + ex2f(-2.8853900817779268f * a)), -1.0f);
}

// ---------- kernel ----------
// B=1048576, T=4, I=2, H=16
// out layout: [hidden_table B*T*H][sum_logits B*T][carry B][output_logits B*5]

__global__ __launch_bounds__(NTHREADS, 2)
void gru_adder_kernel(const float* __restrict__ x,
                      float* __restrict__ out)
{
    // Shared memory: ONLY the per-thread gate scratch (64 KB).
    extern __shared__ __align__(16) char smem_raw[];
    u64* s_nAB = (u64*)smem_raw;              // [k][tid] packed (nA_k, nB_k)
    u64* s_zAB = s_nAB + 16 * NTHREADS;       // [k][tid] packed (zA_k, zB_k)

    const int tid = threadIdx.x;
    const size_t gt = (size_t)blockIdx.x * NTHREADS + tid;
    const size_t b0 = 2 * gt;                  // elems b0, b0+1 per thread

    u64 hA[8], hB[8];                          // packed (h_2p, h_2p+1)
#pragma unroll
    for (int p = 0; p < 8; p++) { hA[p] = 0ull; hB[p] = 0ull; }

    float* outH = out;
    float* outS = out + 67108864ULL;   // + B*T*H
    float* outC = out + 71303168ULL;   // + B*T
    float* outO = out + 72351744ULL;   // + B
    const u64 NEG1 = 0xBF800000BF800000ull;
    const u64 ZERO = 0ull;

#pragma unroll 1
    for (int t = 0; t < 4; t++) {
        float2 xvA = *(const float2*)(x + b0 * 8 + 2 * t);
        float2 xvB = *(const float2*)(x + (b0 + 1) * 8 + 2 * t);
        u64 pxA = pk2(xvA.x, xvA.y);
        u64 pxB = pk2(xvB.x, xvB.y);

        // Gate pass: rolled. All weights/biases from constant memory
        // (warp-uniform affine addresses -> uniform/const port, L1 untouched).
#pragma unroll 1
        for (int k = 0; k < 16; k++) {
            const int jr = k, jz = 16 + k, jn = 32 + k;
            u64 wihR = *(const u64*)&c_wih[2 * jr];
            u64 wihZ = *(const u64*)&c_wih[2 * jz];
            u64 wihN = *(const u64*)&c_wih[2 * jn];
            float brzR = c_bih[jr] + c_bhh[jr];
            float brzZ = c_bih[jz] + c_bhh[jz];
            u64 arA = f2fma(pxA, wihR, pk2(brzR, 0.0f));
            u64 arB = f2fma(pxB, wihR, pk2(brzR, 0.0f));
            u64 azA = f2fma(pxA, wihZ, pk2(brzZ, 0.0f));
            u64 azB = f2fma(pxB, wihZ, pk2(brzZ, 0.0f));
            u64 iNA = f2fma(pxA, wihN, pk2(c_bih[jn], 0.0f));
            u64 iNB = f2fma(pxB, wihN, pk2(c_bih[jn], 0.0f));
            u64 hNA = pk2(c_bhh[jn], 0.0f);
            u64 hNB = hNA;
            const u64* wr = (const u64*)&c_whh[jr * 16];
            const u64* wz = (const u64*)&c_whh[jz * 16];
            const u64* wn = (const u64*)&c_whh[jn * 16];
#pragma unroll
            for (int q = 0; q < 8; q++) {
                u64 a = wr[q];
                u64 c = wz[q];
                u64 e = wn[q];
                arA = f2fma(hA[q], a, arA);
                arB = f2fma(hB[q], a, arB);
                azA = f2fma(hA[q], c, azA);
                azB = f2fma(hB[q], c, azB);
                hNA = f2fma(hA[q], e, hNA);
                hNB = f2fma(hB[q], e, hNB);
            }
            float rA = sigmoidf_(hsum(arA));
            float rB = sigmoidf_(hsum(arB));
            float zA = sigmoidf_(hsum(azA));
            float zB = sigmoidf_(hsum(azB));
            float nA = tanhf_(fmaf(rA, hsum(hNA), hsum(iNA)));
            float nB = tanhf_(fmaf(rB, hsum(hNB), hsum(iNB)));
            s_nAB[k * NTHREADS + tid] = pk2(nA, nB);
            s_zAB[k * NTHREADS + tid] = pk2(zA, zB);
        }

        // Update pass: LDS.64 readback, repack lanes via movs (ALU pipe).
        u64 stA = ZERO, stB = ZERO;
#pragma unroll
        for (int p = 0; p < 8; p++) {
            u64 n0 = s_nAB[(2 * p)     * NTHREADS + tid];
            u64 n1 = s_nAB[(2 * p + 1) * NTHREADS + tid];
            u64 z0 = s_zAB[(2 * p)     * NTHREADS + tid];
            u64 z1 = s_zAB[(2 * p + 1) * NTHREADS + tid];
            float n0l, n0h, n1l, n1h, z0l, z0h, z1l, z1h;
            up2(n0, n0l, n0h); up2(n1, n1l, n1h);
            up2(z0, z0l, z0h); up2(z1, z1l, z1h);
            u64 nnA = pk2(n0l, n1l), nnB = pk2(n0h, n1h);
            u64 zzA = pk2(z0l, z1l), zzB = pk2(z0h, z1h);
            u64 wsp = *(const u64*)&c_wsum[2 * p];
            hA[p] = f2fma(zzA, f2fma(nnA, NEG1, hA[p]), nnA);
            hB[p] = f2fma(zzB, f2fma(nnB, NEG1, hB[p]), nnB);
            stA = f2fma(hA[p], wsp, stA);
            stB = f2fma(hB[p], wsp, stB);
        }
        float slA = c_bsum[0] + hsum(stA);
        float slB = c_bsum[0] + hsum(stB);

        outS[b0 * 4 + t]       = slA;
        outS[(b0 + 1) * 4 + t] = slB;
        outO[b0 * 5 + t]       = slA;
        outO[(b0 + 1) * 5 + t] = slB;

        ulonglong2* phA = (ulonglong2*)(outH + (b0 * 4 + (size_t)t) * 16);
        phA[0] = make_ulonglong2(hA[0], hA[1]);
        phA[1] = make_ulonglong2(hA[2], hA[3]);
        phA[2] = make_ulonglong2(hA[4], hA[5]);
        phA[3] = make_ulonglong2(hA[6], hA[7]);
        ulonglong2* phB = (ulonglong2*)(outH + ((b0 + 1) * 4 + (size_t)t) * 16);
        phB[0] = make_ulonglong2(hB[0], hB[1]);
        phB[1] = make_ulonglong2(hB[2], hB[3]);
        phB[2] = make_ulonglong2(hB[4], hB[5]);
        phB[3] = make_ulonglong2(hB[6], hB[7]);
    }

    // carry logits from h_last
    u64 ccA = ZERO, ccB = ZERO;
#pragma unroll
    for (int p = 0; p < 8; p++) {
        u64 wcp = *(const u64*)&c_wcar[2 * p];
        ccA = f2fma(hA[p], wcp, ccA);
        ccB = f2fma(hB[p], wcp, ccB);
    }
    float cA = c_bcar[0] + hsum(ccA);
    float cB = c_bcar[0] + hsum(ccB);

    outC[b0]               = cA;
    outC[b0 + 1]           = cB;
    outO[b0 * 5 + 4]       = cA;
    outO[(b0 + 1) * 5 + 4] = cB;
}

extern "C" void kernel_launch(void* const* d_in, const int* in_sizes, int n_in,
                              void* d_out, int out_size) {
    const float* x = (const float*)d_in[0];
    // Stage weights into constant memory: async D2D copies (graph-capturable
    // memcpy nodes, no allocation).
    cudaMemcpyToSymbolAsync(c_wih,  d_in[1], 96 * 4,  0, cudaMemcpyDeviceToDevice);
    cudaMemcpyToSymbolAsync(c_whh,  d_in[2], 768 * 4, 0, cudaMemcpyDeviceToDevice);
    cudaMemcpyToSymbolAsync(c_bih,  d_in[3], 48 * 4,  0, cudaMemcpyDeviceToDevice);
    cudaMemcpyToSymbolAsync(c_bhh,  d_in[4], 48 * 4,  0, cudaMemcpyDeviceToDevice);
    cudaMemcpyToSymbolAsync(c_wsum, d_in[5], 16 * 4,  0, cudaMemcpyDeviceToDevice);
    cudaMemcpyToSymbolAsync(c_bsum, d_in[6], 1 * 4,   0, cudaMemcpyDeviceToDevice);
    cudaMemcpyToSymbolAsync(c_wcar, d_in[7], 16 * 4,  0, cudaMemcpyDeviceToDevice);
    cudaMemcpyToSymbolAsync(c_bcar, d_in[8], 1 * 4,   0, cudaMemcpyDeviceToDevice);

    float* out = (float*)d_out;
    const int smem_bytes = 2 * 16 * NTHREADS * 8;  // 65536: n/z scratch only
    cudaFuncSetAttribute(gru_adder_kernel,
                         cudaFuncAttributeMaxDynamicSharedMemorySize, smem_bytes);
    gru_adder_kernel<<<GRID_BLOCKS, NTHREADS, smem_bytes>>>(x, out);
}

// round 12
// speedup vs baseline: 1.2916x; 1.2916x over previous
#include <cuda_runtime.h>

typedef unsigned long long u64;

#define NTHREADS 256
#define GRID_BLOCKS 2048   // 1048576 elems / (2 per thread * 256)

// ---------- weights in constant memory (uniform-port loads) ----------
__constant__ __align__(16) float c_wih[96];    // [48][2] row-major
__constant__ __align__(16) float c_whh[768];   // [48][16] row-major
__constant__ __align__(16) float c_bih[48];
__constant__ __align__(16) float c_bhh[48];
__constant__ __align__(16) float c_wsum[16];
__constant__ __align__(16) float c_wcar[16];
__constant__ float c_bsum[1];
__constant__ float c_bcar[1];

// ---------- packed f32x2 + approx-math helpers ----------
__device__ __forceinline__ u64 f2fma(u64 a, u64 b, u64 c) {
    u64 d; asm("fma.rn.f32x2 %0, %1, %2, %3;" : "=l"(d) : "l"(a), "l"(b), "l"(c)); return d;
}
__device__ __forceinline__ u64 pk2(float lo, float hi) {
    u64 d; asm("mov.b64 %0, {%1,%2};" : "=l"(d) : "f"(lo), "f"(hi)); return d;
}
__device__ __forceinline__ void up2(u64 a, float& lo, float& hi) {
    asm("mov.b64 {%0,%1}, %2;" : "=f"(lo), "=f"(hi) : "l"(a));
}
__device__ __forceinline__ float hsum(u64 a) {   // lo + hi
    float lo, hi; up2(a, lo, hi); return lo + hi;
}
__device__ __forceinline__ float ex2f(float x) {
    float y; asm("ex2.approx.f32 %0, %1;" : "=f"(y) : "f"(x)); return y;
}
__device__ __forceinline__ float rcpf(float x) {
    float y; asm("rcp.approx.f32 %0, %1;" : "=f"(y) : "f"(x)); return y;
}
__device__ __forceinline__ float sigmoidf_(float a) {
    return rcpf(1.0f + ex2f(-1.4426950408889634f * a));
}
__device__ __forceinline__ float tanhf_(float a) {
    return fmaf(2.0f, rcpf(1.0f + ex2f(-2.8853900817779268f * a)), -1.0f);
}

// ---------- kernel ----------
// B=1048576, T=4, I=2, H=16
// out layout: [hidden_table B*T*H][sum_logits B*T][carry B][output_logits B*5]

__global__ __launch_bounds__(NTHREADS, 3)   // 85-reg cap, 3 CTAs/SM target
void gru_adder_kernel(const float* __restrict__ x,
                      float* __restrict__ out)
{
    // Shared memory: single packed h/hn scratch (32 KB/CTA).
    extern __shared__ __align__(16) char smem_raw[];
    u64* s_h = (u64*)smem_raw;                // [k][tid] packed (hA_k, hB_k)

    const int tid = threadIdx.x;
    const size_t gt = (size_t)blockIdx.x * NTHREADS + tid;
    const size_t b0 = 2 * gt;                  // elems b0, b0+1 per thread

    // h state: packed registers for FMAs + smem scalar mirror for the update.
    u64 hA[8], hB[8];                          // (h_2p, h_2p+1) per element
#pragma unroll
    for (int p = 0; p < 8; p++) { hA[p] = 0ull; hB[p] = 0ull; }
#pragma unroll
    for (int k = 0; k < 16; k++) s_h[k * NTHREADS + tid] = 0ull;   // own slots

    float* outH = out;
    float* outS = out + 67108864ULL;   // + B*T*H
    float* outC = out + 71303168ULL;   // + B*T
    float* outO = out + 72351744ULL;   // + B
    const u64 ZERO = 0ull;

#pragma unroll 1
    for (int t = 0; t < 4; t++) {
        float2 xvA = *(const float2*)(x + b0 * 8 + 2 * t);
        float2 xvB = *(const float2*)(x + (b0 + 1) * 8 + 2 * t);
        u64 pxA = pk2(xvA.x, xvA.y);
        u64 pxB = pk2(xvB.x, xvB.y);

        // Gate pass: rolled. Weights from const memory (uniform port).
        // h-update fused: scratch slot k holds old h_k, gets new h_k.
#pragma unroll 1
        for (int k = 0; k < 16; k++) {
            const int jr = k, jz = 16 + k, jn = 32 + k;
            u64 wihR = *(const u64*)&c_wih[2 * jr];
            u64 wihZ = *(const u64*)&c_wih[2 * jz];
            u64 wihN = *(const u64*)&c_wih[2 * jn];
            float brzR = c_bih[jr] + c_bhh[jr];
            float brzZ = c_bih[jz] + c_bhh[jz];
            u64 arA = f2fma(pxA, wihR, pk2(brzR, 0.0f));
            u64 arB = f2fma(pxB, wihR, pk2(brzR, 0.0f));
            u64 azA = f2fma(pxA, wihZ, pk2(brzZ, 0.0f));
            u64 azB = f2fma(pxB, wihZ, pk2(brzZ, 0.0f));
            u64 iNA = f2fma(pxA, wihN, pk2(c_bih[jn], 0.0f));
            u64 iNB = f2fma(pxB, wihN, pk2(c_bih[jn], 0.0f));
            u64 hNA = pk2(c_bhh[jn], 0.0f);
            u64 hNB = hNA;
            const u64* wr = (const u64*)&c_whh[jr * 16];
            const u64* wz = (const u64*)&c_whh[jz * 16];
            const u64* wn = (const u64*)&c_whh[jn * 16];
#pragma unroll
            for (int q = 0; q < 8; q++) {
                u64 a = wr[q];
                u64 c = wz[q];
                u64 e = wn[q];
                arA = f2fma(hA[q], a, arA);
                arB = f2fma(hB[q], a, arB);
                azA = f2fma(hA[q], c, azA);
                azB = f2fma(hB[q], c, azB);
                hNA = f2fma(hA[q], e, hNA);
                hNB = f2fma(hB[q], e, hNB);
            }
            float rA = sigmoidf_(hsum(arA));
            float rB = sigmoidf_(hsum(arB));
            float zA = sigmoidf_(hsum(azA));
            float zB = sigmoidf_(hsum(azB));
            float nA = tanhf_(fmaf(rA, hsum(hNA), hsum(iNA)));
            float nB = tanhf_(fmaf(rB, hsum(hNB), hsum(iNB)));
            // fused h-update: old h_k comes from the scratch slot
            u64 hold = s_h[k * NTHREADS + tid];
            float holdA, holdB; up2(hold, holdA, holdB);
            float hnA = fmaf(zA, holdA - nA, nA);   // (1-z)n + z h
            float hnB = fmaf(zB, holdB - nB, nB);
            s_h[k * NTHREADS + tid] = pk2(hnA, hnB);
        }

        // Rebuild packed h registers + sum logits, then store hidden rows.
        u64 stA = ZERO, stB = ZERO;
#pragma unroll
        for (int p = 0; p < 8; p++) {
            u64 v0 = s_h[(2 * p)     * NTHREADS + tid];
            u64 v1 = s_h[(2 * p + 1) * NTHREADS + tid];
            float a0, b0f, a1, b1f;
            up2(v0, a0, b0f); up2(v1, a1, b1f);
            hA[p] = pk2(a0, a1);
            hB[p] = pk2(b0f, b1f);
            u64 wsp = *(const u64*)&c_wsum[2 * p];
            stA = f2fma(hA[p], wsp, stA);
            stB = f2fma(hB[p], wsp, stB);
        }
        float slA = c_bsum[0] + hsum(stA);
        float slB = c_bsum[0] + hsum(stB);

        outS[b0 * 4 + t]       = slA;
        outS[(b0 + 1) * 4 + t] = slB;
        outO[b0 * 5 + t]       = slA;
        outO[(b0 + 1) * 5 + t] = slB;

        ulonglong2* phA = (ulonglong2*)(outH + (b0 * 4 + (size_t)t) * 16);
        phA[0] = make_ulonglong2(hA[0], hA[1]);
        phA[1] = make_ulonglong2(hA[2], hA[3]);
        phA[2] = make_ulonglong2(hA[4], hA[5]);
        phA[3] = make_ulonglong2(hA[6], hA[7]);
        ulonglong2* phB = (ulonglong2*)(outH + ((b0 + 1) * 4 + (size_t)t) * 16);
        phB[0] = make_ulonglong2(hB[0], hB[1]);
        phB[1] = make_ulonglong2(hB[2], hB[3]);
        phB[2] = make_ulonglong2(hB[4], hB[5]);
        phB[3] = make_ulonglong2(hB[6], hB[7]);
    }

    // carry logits from h_last
    u64 ccA = ZERO, ccB = ZERO;
#pragma unroll
    for (int p = 0; p < 8; p++) {
        u64 wcp = *(const u64*)&c_wcar[2 * p];
        ccA = f2fma(hA[p], wcp, ccA);
        ccB = f2fma(hB[p], wcp, ccB);
    }
    float cA = c_bcar[0] + hsum(ccA);
    float cB = c_bcar[0] + hsum(ccB);

    outC[b0]               = cA;
    outC[b0 + 1]           = cB;
    outO[b0 * 5 + 4]       = cA;
    outO[(b0 + 1) * 5 + 4] = cB;
}

extern "C" void kernel_launch(void* const* d_in, const int* in_sizes, int n_in,
                              void* d_out, int out_size) {
    const float* x = (const float*)d_in[0];
    // Stage weights into constant memory: async D2D copies (graph-capturable
    // memcpy nodes, no allocation).
    cudaMemcpyToSymbolAsync(c_wih,  d_in[1], 96 * 4,  0, cudaMemcpyDeviceToDevice);
    cudaMemcpyToSymbolAsync(c_whh,  d_in[2], 768 * 4, 0, cudaMemcpyDeviceToDevice);
    cudaMemcpyToSymbolAsync(c_bih,  d_in[3], 48 * 4,  0, cudaMemcpyDeviceToDevice);
    cudaMemcpyToSymbolAsync(c_bhh,  d_in[4], 48 * 4,  0, cudaMemcpyDeviceToDevice);
    cudaMemcpyToSymbolAsync(c_wsum, d_in[5], 16 * 4,  0, cudaMemcpyDeviceToDevice);
    cudaMemcpyToSymbolAsync(c_bsum, d_in[6], 1 * 4,   0, cudaMemcpyDeviceToDevice);
    cudaMemcpyToSymbolAsync(c_wcar, d_in[7], 16 * 4,  0, cudaMemcpyDeviceToDevice);
    cudaMemcpyToSymbolAsync(c_bcar, d_in[8], 1 * 4,   0, cudaMemcpyDeviceToDevice);

    float* out = (float*)d_out;
    const int smem_bytes = 16 * NTHREADS * 8;  // 32768: single hn scratch
    cudaFuncSetAttribute(gru_adder_kernel,
                         cudaFuncAttributeMaxDynamicSharedMemorySize, smem_bytes);
    gru_adder_kernel<<<GRID_BLOCKS, NTHREADS, smem_bytes>>>(x, out);
}